// round 5
// baseline (speedup 1.0000x reference)
#include <cuda_runtime.h>

#define NN    64          // nodes per graph
#define HID   32
#define NE    1024        // edges per graph
#define NF    3
#define NROWS (NE + NF)   // 1027
#define T     512
#define MT_STRIDE 36      // padded transposed-M row stride (bank-conflict-free)

// batch-invariant scratch (edge list & weights identical for every graph)
__device__ int   g_off[NN + 1];
__device__ int   g_rank[NE];              // CSR slot of original edge e
__device__ float g_M1t[HID * MT_STRIDE];  // (W2 @ Wl[4:36])^T, padded
__device__ float g_M2t[HID * MT_STRIDE];  // (W2 @ Wl[40:72])^T, padded
__device__ float g_c1[HID];               // b2 @ Wl[4:36]
__device__ float g_c2[HID];               // b2 @ Wl[40:72]

// ---------------------------------------------------------------------------
// Kernel 0: CSR rank build (deterministic stable counting sort) + weight fold.
// ---------------------------------------------------------------------------
__global__ void setup_kernel(const int* __restrict__ esrc,
                             const int* __restrict__ edst,
                             const float* __restrict__ W2,
                             const float* __restrict__ Wl,
                             const float* __restrict__ b2) {
    __shared__ int cnt[NN];
    __shared__ int offs[NN + 1];
    __shared__ int cnt2[NN];
    int t = threadIdx.x;            // blockDim = 1024
    if (t < NN) { cnt[t] = 0; cnt2[t] = 0; }
    __syncthreads();
    atomicAdd(&cnt[esrc[t]], 1);
    __syncthreads();
    if (t == 0) {
        int acc = 0;
        for (int n = 0; n < NN; n++) { offs[n] = acc; acc += cnt[n]; }
        offs[NN] = acc;
    }
    __syncthreads();
    if (t < 32) {
        for (int c = 0; c < NE / 32; c++) {
            int e = c * 32 + t;
            int s = esrc[e];
            unsigned m = __match_any_sync(0xffffffffu, s);
            int within = __popc(m & ((1u << t) - 1u));
            int base = cnt2[s];
            __syncwarp();
            g_rank[e] = offs[s] + base + within;
            if (within == 0) cnt2[s] = base + __popc(m);
            __syncwarp();
        }
    }
    if (t <= NN) g_off[t] = offs[t];

    // fold W2 through Wl, stored TRANSPOSED: M1t[k, j] = sum_i W2[j,i]*Wl[4+i,k]
    int j = t >> 5, k = t & 31;     // j = H-channel, k = output channel
    float a1 = 0.f, a2 = 0.f;
    for (int i = 0; i < 32; i++) {
        float w2 = W2[j * 32 + i];
        a1 = fmaf(w2, Wl[(4  + i) * 32 + k], a1);
        a2 = fmaf(w2, Wl[(40 + i) * 32 + k], a2);
    }
    g_M1t[k * MT_STRIDE + j] = a1;
    g_M2t[k * MT_STRIDE + j] = a2;
    if (t < 32) {
        float c1 = 0.f, c2 = 0.f;
        for (int i = 0; i < 32; i++) {
            c1 = fmaf(b2[i], Wl[(4  + i) * 32 + t], c1);
            c2 = fmaf(b2[i], Wl[(40 + i) * 32 + t], c2);
        }
        g_c1[t] = c1;
        g_c2[t] = c2;
    }
}

// ---------------------------------------------------------------------------
// Kernel 1: one block per graph. ~71 KB smem -> 3 blocks/SM.
// ---------------------------------------------------------------------------
#define SMEM_WORDS 17752
#define SMEM_BYTES (SMEM_WORDS * 4)

__global__ __launch_bounds__(T, 3) void critic_kernel(
    const float* __restrict__ x,         // [B*64, 4]
    const float* __restrict__ edge_attr, // [B*1024, 2]
    const float* __restrict__ action,    // [B, 1027]
    const int*   __restrict__ edst,      // [1024]
    const float* __restrict__ W1,        // [10,32]
    const float* __restrict__ b1,        // [32]
    const float* __restrict__ Wl,        // [73,32]
    const float* __restrict__ bl,        // [32]
    const float* __restrict__ Wv,        // [32]
    const float* __restrict__ bv,        // [1]
    float* __restrict__ out)             // [B]
{
    extern __shared__ float sm[];
    float* W1s   = sm;          // 320
    float* b1s   = sm + 320;    // 32
    float* Xl1   = sm + 352;    // 128 (Wl rows 0..3)
    float* Xl2   = sm + 480;    // 128 (Wl rows 36..39)
    float* wl72s = sm + 608;    // 32
    float* bls   = sm + 640;    // 32
    float* Wvs   = sm + 672;    // 32
    float* c1s   = sm + 704;    // 32
    float* c2s   = sm + 736;    // 32
    float* xs    = sm + 768;    // 256
    float* M1ts  = sm + 1024;   // 1152 (32 x 36 padded, transposed)
    float* M2ts  = sm + 2176;   // 1152
    float* p1s   = sm + 3328;   // 2048
    float* p2s   = sm + 5376;   // 2048
    float* Hs    = sm + 7424;   // 2048
    float* g1s   = sm + 9472;   // 2048
    float* g2s   = sm + 11520;  // 2048
    float* ecf   = sm + 13568;  // 4096 (float4[1024]: ea0, ea1, dstIdx*32, act)
    float* facta = sm + 17664;  // 4
    float* wsum  = sm + 17668;  // 16
    int*   offs  = (int*)(sm + 17684); // 68
    float4* ecomb = (float4*)ecf;

    const int b   = blockIdx.x;
    const int tid = threadIdx.x;
    const int w   = tid >> 5;
    const int k   = tid & 31;
    const int e   = k >> 3;        // edge slot within quad
    const int q   = k & 7;         // channel group (channels 4q..4q+3)
    const int q4  = q << 2;

    // ---- cooperative loads (all coalesced) ----
    for (int i = tid; i < 320; i += T) W1s[i] = W1[i];
    if (tid < 128) { Xl1[tid] = Wl[tid]; Xl2[tid] = Wl[36 * 32 + tid]; }
    if (tid < 32) {
        b1s[tid]   = b1[tid];
        wl72s[tid] = Wl[72 * 32 + tid];
        bls[tid]   = bl[tid];
        Wvs[tid]   = Wv[tid];
        c1s[tid]   = g_c1[tid];
        c2s[tid]   = g_c2[tid];
    }
    for (int i = tid; i < HID * MT_STRIDE; i += T) {
        M1ts[i] = g_M1t[i];
        M2ts[i] = g_M2t[i];
    }
    for (int i = tid; i < 256; i += T) xs[i] = x[b * 256 + i];
    for (int i = tid; i < NE; i += T) {
        int   rk = g_rank[i];                               // coalesced
        float2 v = ((const float2*)edge_attr)[b * NE + i];  // coalesced
        float  a = action[b * NROWS + i];                   // coalesced
        int    d = edst[i];                                 // coalesced
        ecomb[rk] = make_float4(v.x, v.y, __int_as_float(d << 5), a);
    }
    if (tid < NF) facta[tid] = action[b * NROWS + NE + tid];
    if (tid <= NN) offs[tid] = g_off[tid];
    __syncthreads();

    // ---- per-node precomputes: p1,p2 (EdgeConv layer1), g init (x part) ----
    for (int i = tid; i < NN * HID; i += T) {
        int n = i >> 5, j = i & 31;
        float4 xv = *(const float4*)(xs + n * 4);
        p1s[i] = fmaf(xv.x, W1s[j],       fmaf(xv.y, W1s[32 + j],
                 fmaf(xv.z, W1s[64 + j],  fmaf(xv.w, W1s[96 + j], b1s[j]))));
        p2s[i] = fmaf(xv.x, W1s[128 + j], fmaf(xv.y, W1s[160 + j],
                 fmaf(xv.z, W1s[192 + j], xv.w * W1s[224 + j])));
        g1s[i] = fmaf(xv.x, Xl1[j],       fmaf(xv.y, Xl1[32 + j],
                 fmaf(xv.z, Xl1[64 + j],  fmaf(xv.w, Xl1[96 + j], bls[j]))));
        g2s[i] = fmaf(xv.x, Xl2[j],       fmaf(xv.y, Xl2[32 + j],
                 fmaf(xv.z, Xl2[64 + j],  xv.w * Xl2[96 + j])));
    }
    __syncthreads();

    // ---- H[n,k] = sum_{edges of n} relu(p1[n]+p2[dst]+ea@W1[8:10]) ----
    // quarter-warp: lane = 8e+q processes edge slot e, channels 4q..4q+3
    {
        float4 w8q = *(const float4*)(W1s + 256 + q4);
        float4 w9q = *(const float4*)(W1s + 288 + q4);
        #pragma unroll
        for (int nn = 0; nn < 4; nn++) {
            int n = w * 4 + nn;
            int beg = offs[n], end = offs[n + 1];
            float4 p1v = *(const float4*)(p1s + n * 32 + q4);
            float4 acc = make_float4(0.f, 0.f, 0.f, 0.f);
            #pragma unroll 2
            for (int i0 = beg; i0 < end; i0 += 4) {
                int i = min(i0 + e, end - 1);              // clamped, always valid
                float4 ec = ecomb[i];                      // 4x16B -> 1 wf
                int didx = __float_as_int(ec.z);           // dst*32
                float4 p2v = *(const float4*)(p2s + didx + q4);
                float4 pre;
                pre.x = fmaf(ec.x, w8q.x, fmaf(ec.y, w9q.x, p1v.x + p2v.x));
                pre.y = fmaf(ec.x, w8q.y, fmaf(ec.y, w9q.y, p1v.y + p2v.y));
                pre.z = fmaf(ec.x, w8q.z, fmaf(ec.y, w9q.z, p1v.z + p2v.z));
                pre.w = fmaf(ec.x, w8q.w, fmaf(ec.y, w9q.w, p1v.w + p2v.w));
                if (i0 + e < end) {
                    acc.x += fmaxf(pre.x, 0.f);
                    acc.y += fmaxf(pre.y, 0.f);
                    acc.z += fmaxf(pre.z, 0.f);
                    acc.w += fmaxf(pre.w, 0.f);
                }
            }
            // reduce over edge slots e (xor 8 and 16 flip e bits)
            acc.x += __shfl_xor_sync(0xffffffffu, acc.x, 8);
            acc.y += __shfl_xor_sync(0xffffffffu, acc.y, 8);
            acc.z += __shfl_xor_sync(0xffffffffu, acc.z, 8);
            acc.w += __shfl_xor_sync(0xffffffffu, acc.w, 8);
            acc.x += __shfl_xor_sync(0xffffffffu, acc.x, 16);
            acc.y += __shfl_xor_sync(0xffffffffu, acc.y, 16);
            acc.z += __shfl_xor_sync(0xffffffffu, acc.z, 16);
            acc.w += __shfl_xor_sync(0xffffffffu, acc.w, 16);
            if (e == 0)
                *(float4*)(Hs + n * 32 + q4) = acc;
        }
    }
    __syncthreads();

    // ---- g{1,2}[n,k] += H[n]@M{1,2} + deg*c{1,2}; warps 0-7: g1, 8-15: g2 ----
    {
        int hf = w >> 3, wl_ = w & 7;
        const float* Mts = hf ? M2ts : M1ts;
        float*       gsd = hf ? g2s : g1s;
        float ck = hf ? c2s[k] : c1s[k];
        float Mreg[32];
        const float4* mp = (const float4*)(Mts + k * MT_STRIDE);
        #pragma unroll
        for (int q2 = 0; q2 < 8; q2++) {                  // 8 LDS.128, padded
            float4 mv = mp[q2];
            Mreg[4*q2+0] = mv.x; Mreg[4*q2+1] = mv.y;
            Mreg[4*q2+2] = mv.z; Mreg[4*q2+3] = mv.w;
        }
        #pragma unroll
        for (int nn = 0; nn < 8; nn++) {
            int n = wl_ * 8 + nn;
            float acc = fmaf((float)(offs[n + 1] - offs[n]), ck, gsd[n * 32 + k]);
            const float4* hp = (const float4*)(Hs + n * 32);
            #pragma unroll
            for (int q2 = 0; q2 < 8; q2++) {
                float4 hv = hp[q2];                        // LDS.128 broadcast
                acc = fmaf(hv.x, Mreg[4 * q2 + 0], acc);
                acc = fmaf(hv.y, Mreg[4 * q2 + 1], acc);
                acc = fmaf(hv.z, Mreg[4 * q2 + 2], acc);
                acc = fmaf(hv.w, Mreg[4 * q2 + 3], acc);
            }
            gsd[n * 32 + k] = acc;
        }
    }
    __syncthreads();

    // ---- rows (CSR order): v = relu(g1[src]+g2[dst]+act*wl72) @ Wv ----
    {
        float4 wlq = *(const float4*)(wl72s + q4);
        float4 wvq = *(const float4*)(Wvs + q4);
        float4 va = make_float4(0.f, 0.f, 0.f, 0.f);
        #pragma unroll
        for (int nn = 0; nn < 4; nn++) {
            int n = w * 4 + nn;
            int beg = offs[n], end = offs[n + 1];
            float4 g1v = *(const float4*)(g1s + n * 32 + q4);
            #pragma unroll 2
            for (int i0 = beg; i0 < end; i0 += 4) {
                int i = min(i0 + e, end - 1);
                float4 ec = ecomb[i];
                int didx = __float_as_int(ec.z);
                float4 g2v = *(const float4*)(g2s + didx + q4);
                float4 pre;
                pre.x = fmaf(ec.w, wlq.x, g1v.x) + g2v.x;
                pre.y = fmaf(ec.w, wlq.y, g1v.y) + g2v.y;
                pre.z = fmaf(ec.w, wlq.z, g1v.z) + g2v.z;
                pre.w = fmaf(ec.w, wlq.w, g1v.w) + g2v.w;
                if (i0 + e < end) {
                    va.x = fmaf(fmaxf(pre.x, 0.f), wvq.x, va.x);
                    va.y = fmaf(fmaxf(pre.y, 0.f), wvq.y, va.y);
                    va.z = fmaf(fmaxf(pre.z, 0.f), wvq.z, va.z);
                    va.w = fmaf(fmaxf(pre.w, 0.f), wvq.w, va.w);
                }
            }
        }
        if (w < NF && e == 0) {                    // factory rows (tiny)
            int n = NN - NF + w;
            float fa = facta[w];
            float4 g1v = *(const float4*)(g1s + n * 32 + q4);
            float4 g2v = *(const float4*)(g2s + n * 32 + q4);
            float4 pre;
            pre.x = fmaf(fa, wlq.x, g1v.x) + g2v.x;
            pre.y = fmaf(fa, wlq.y, g1v.y) + g2v.y;
            pre.z = fmaf(fa, wlq.z, g1v.z) + g2v.z;
            pre.w = fmaf(fa, wlq.w, g1v.w) + g2v.w;
            va.x = fmaf(fmaxf(pre.x, 0.f), wvq.x, va.x);
            va.y = fmaf(fmaxf(pre.y, 0.f), wvq.y, va.y);
            va.z = fmaf(fmaxf(pre.z, 0.f), wvq.z, va.z);
            va.w = fmaf(fmaxf(pre.w, 0.f), wvq.w, va.w);
        }
        float vacc = (va.x + va.y) + (va.z + va.w);
        #pragma unroll
        for (int o = 16; o > 0; o >>= 1)
            vacc += __shfl_xor_sync(0xffffffffu, vacc, o);
        if (k == 0) wsum[w] = vacc;
    }
    __syncthreads();
    if (tid == 0) {
        float tot = 0.f;
        #pragma unroll
        for (int i = 0; i < 16; i++) tot += wsum[i];
        out[b] = tot + (float)NROWS * bv[0];
    }
}

// ---------------------------------------------------------------------------
extern "C" void kernel_launch(void* const* d_in, const int* in_sizes, int n_in,
                              void* d_out, int out_size) {
    const float* x         = (const float*)d_in[0];
    // d_in[1] = edge_index: redundant, unused
    const float* edge_attr = (const float*)d_in[2];
    const float* action    = (const float*)d_in[3];
    const int*   esrc      = (const int*)d_in[4];
    const int*   edst      = (const int*)d_in[5];
    const float* W1        = (const float*)d_in[6];
    const float* b1        = (const float*)d_in[7];
    const float* W2        = (const float*)d_in[8];
    const float* b2        = (const float*)d_in[9];
    const float* Wl        = (const float*)d_in[10];
    const float* bl        = (const float*)d_in[11];
    const float* Wv        = (const float*)d_in[12];
    const float* bv        = (const float*)d_in[13];
    float* out = (float*)d_out;

    cudaFuncSetAttribute(critic_kernel,
                         cudaFuncAttributeMaxDynamicSharedMemorySize,
                         SMEM_BYTES);

    setup_kernel<<<1, 1024>>>(esrc, edst, W2, Wl, b2);
    critic_kernel<<<out_size, T, SMEM_BYTES>>>(
        x, edge_attr, action, edst, W1, b1, Wl, bl, Wv, bv, out);
}